// round 7
// baseline (speedup 1.0000x reference)
#include <cuda_runtime.h>
#include <cuda_bf16.h>

#define BB 64
#define SS 2048
#define RR 1024
#define HH 512
#define NSPLIT 8                 // softmax-prologue per-thread ownership factor
#define RSPLIT 8                 // column chunks in k4
#define CCHUNK4 (RR / 4 / RSPLIT)  // 32 float4 columns per block

// Scratch (allocation-free rule: __device__ globals)
__device__ float g_att_h[BB * HH];   // 128 KB
__device__ float g_score[BB * SS];   // 512 KB (raw scores; softmax fused into k4)

__device__ __forceinline__ float fast_tanh(float x) {
    float y;
    asm("tanh.approx.f32 %0, %1;" : "=f"(y) : "f"(x));
    return y;
}

// ---------------------------------------------------------------------------
// K1: att_h[b,j] = dot(h[b,:], W[j,:]) + bias[j]
// grid (B, 64), block 256 (8 warps, one output j per warp)
// ---------------------------------------------------------------------------
__global__ void k1_att_h(const float* __restrict__ h,
                         const float* __restrict__ W,
                         const float* __restrict__ bias) {
    const int b    = blockIdx.x;
    const int warp = threadIdx.x >> 5;
    const int lane = threadIdx.x & 31;

    __shared__ float sh[RR];
    for (int i = threadIdx.x; i < RR / 4; i += blockDim.x)
        ((float4*)sh)[i] = ((const float4*)(h + (size_t)b * RR))[i];
    __syncthreads();

    const int j = blockIdx.y * 8 + warp;
    const float4* Wr = (const float4*)(W + (size_t)j * RR);

    float acc = 0.f;
#pragma unroll
    for (int i = 0; i < RR / 128; i++) {           // 8 iterations
        float4 w4 = Wr[i * 32 + lane];
        int k = (i * 32 + lane) * 4;
        acc += w4.x * sh[k] + w4.y * sh[k + 1] + w4.z * sh[k + 2] + w4.w * sh[k + 3];
    }
#pragma unroll
    for (int o = 16; o; o >>= 1) acc += __shfl_down_sync(0xFFFFFFFFu, acc, o);
    if (lane == 0) g_att_h[b * HH + j] = acc + bias[j];
}

// ---------------------------------------------------------------------------
// K2: score[b,s] = sum_h tanh(p[b,s,h] + att_h[b,h]) * w_alpha[h]
// (b_alpha dropped: a constant shift cancels in softmax)
// grid (B, S/8), block 256 (8 warps, one s per warp). 256 MB streaming read.
// tanh via MUFU.TANH so the kernel stays HBM-bound.
// ---------------------------------------------------------------------------
__global__ void k2_scores(const float* __restrict__ p,
                          const float* __restrict__ w_alpha) {
    const int b = blockIdx.x;

    __shared__ float s_ah[HH];
    __shared__ float s_wa[HH];
    for (int i = threadIdx.x; i < HH / 4; i += blockDim.x) {
        ((float4*)s_ah)[i] = ((const float4*)(g_att_h + (size_t)b * HH))[i];
        ((float4*)s_wa)[i] = ((const float4*)w_alpha)[i];
    }
    __syncthreads();

    const int warp = threadIdx.x >> 5;
    const int lane = threadIdx.x & 31;
    const int s    = blockIdx.y * 8 + warp;

    const float4* pr = (const float4*)(p + ((size_t)b * SS + s) * HH);

    float acc = 0.f;
#pragma unroll
    for (int i = 0; i < HH / 128; i++) {           // 4 iterations
        float4 p4 = pr[i * 32 + lane];
        int k = (i * 32 + lane) * 4;
        acc += fast_tanh(p4.x + s_ah[k])     * s_wa[k];
        acc += fast_tanh(p4.y + s_ah[k + 1]) * s_wa[k + 1];
        acc += fast_tanh(p4.z + s_ah[k + 2]) * s_wa[k + 2];
        acc += fast_tanh(p4.w + s_ah[k + 3]) * s_wa[k + 3];
    }
#pragma unroll
    for (int o = 16; o; o >>= 1) acc += __shfl_down_sync(0xFFFFFFFFu, acc, o);
    if (lane == 0) g_score[b * SS + s] = acc;
}

// ---------------------------------------------------------------------------
// K4: fused softmax + weighted sum, R-split — writes final output directly.
// grid (B, RSPLIT), block 256.
// Prologue: each block computes the batch row's masked softmax into smem
// (16 KB scores+mask reads, 2048 exp — redundant across the 8 sp-blocks, cheap).
// softmax -> *mask -> renorm  ==  e_i*m_i / sum_j(e_j*m_j)  (max-subtracted).
// Main loop: 8 warps = 8 s-lanes of 256 steps; each lane owns one float4
// column of this block's 128-float column chunk. Each warp-load = contiguous
// 512 B. Epilogue: 8-way smem reduce across warps, direct store to d_out.
// ---------------------------------------------------------------------------
__global__ void k4_wsum(const float* __restrict__ feats,
                        const int* __restrict__ mask,
                        float* __restrict__ out) {
    const int b     = blockIdx.x;
    const int sp    = blockIdx.y;        // column chunk 0..7
    const int tid   = threadIdx.x;
    const int lane  = tid & 31;          // float4 column within chunk
    const int slane = tid >> 5;          // s-lane (warp) 0..7

    __shared__ float  sw[SS];            // 8 KB: full row of weights
    __shared__ float  red[8];
    __shared__ float4 sred[8][32];       // 4 KB: per-warp partial outputs

    // --- load all SS scores for this batch row: thread tid owns tid + k*256
    float v[NSPLIT];
    int   m[NSPLIT];
#pragma unroll
    for (int k = 0; k < NSPLIT; k++) {
        v[k] = g_score[b * SS + k * 256 + tid];
        m[k] = mask[b * SS + k * 256 + tid];
    }

    // --- block max (over all scores, matching reference stability)
    float mx = v[0];
#pragma unroll
    for (int k = 1; k < NSPLIT; k++) mx = fmaxf(mx, v[k]);
#pragma unroll
    for (int o = 16; o; o >>= 1) mx = fmaxf(mx, __shfl_xor_sync(0xFFFFFFFFu, mx, o));
    if (lane == 0) red[slane] = mx;
    __syncthreads();
    mx = fmaxf(fmaxf(fmaxf(red[0], red[1]), fmaxf(red[2], red[3])),
               fmaxf(fmaxf(red[4], red[5]), fmaxf(red[6], red[7])));
    __syncthreads();

    // --- masked exponentials + block sum
    float e[NSPLIT];
    float sum = 0.f;
#pragma unroll
    for (int k = 0; k < NSPLIT; k++) {
        e[k] = m[k] ? __expf(v[k] - mx) : 0.f;
        sum += e[k];
    }
#pragma unroll
    for (int o = 16; o; o >>= 1) sum += __shfl_xor_sync(0xFFFFFFFFu, sum, o);
    if (lane == 0) red[slane] = sum;
    __syncthreads();
    sum = red[0] + red[1] + red[2] + red[3] + red[4] + red[5] + red[6] + red[7];
    const float inv = 1.f / sum;

#pragma unroll
    for (int k = 0; k < NSPLIT; k++) sw[k * 256 + tid] = e[k] * inv;
    __syncthreads();

    // --- streaming weighted sum: warp slane covers s in [slane*256, slane*256+256)
    const float4* base = (const float4*)(feats + ((size_t)b * SS + slane * 256) * RR)
                         + sp * CCHUNK4 + lane;
    const float* wrow = sw + slane * 256;

    float4 acc = make_float4(0.f, 0.f, 0.f, 0.f);
#pragma unroll 8
    for (int i = 0; i < 256; i++) {
        float4 f = base[(size_t)i * (RR / 4)];
        float w = wrow[i];
        acc.x += w * f.x; acc.y += w * f.y; acc.z += w * f.z; acc.w += w * f.w;
    }

    // --- reduce across the 8 s-lanes, store final output
    sred[slane][lane] = acc;
    __syncthreads();
    if (slane == 0) {
        float4 a = sred[0][lane];
#pragma unroll
        for (int k = 1; k < 8; k++) {
            float4 f = sred[k][lane];
            a.x += f.x; a.y += f.y; a.z += f.z; a.w += f.w;
        }
        ((float4*)(out + (size_t)b * RR))[sp * CCHUNK4 + lane] = a;
    }
}

// ---------------------------------------------------------------------------
extern "C" void kernel_launch(void* const* d_in, const int* in_sizes, int n_in,
                              void* d_out, int out_size) {
    const float* h         = (const float*)d_in[0];
    const float* att_feats = (const float*)d_in[1];
    const float* p_att     = (const float*)d_in[2];
    const int*   masks     = (const int*)  d_in[3];
    const float* W         = (const float*)d_in[4];
    const float* b_h2att   = (const float*)d_in[5];
    const float* w_alpha   = (const float*)d_in[6];
    // d_in[7] = b_alpha: unused (constant shift cancels in softmax)
    float*       out       = (float*)d_out;

    k1_att_h  <<<dim3(BB, HH / 8), 256>>>(h, W, b_h2att);
    k2_scores <<<dim3(BB, SS / 8), 256>>>(p_att, w_alpha);
    k4_wsum   <<<dim3(BB, RSPLIT), 256>>>(att_feats, masks, out);
}

// round 8
// speedup vs baseline: 1.0987x; 1.0987x over previous
#include <cuda_runtime.h>
#include <cuda_bf16.h>

#define BB 64
#define SS 2048
#define RR 1024
#define HH 512
#define NSPLIT 8
#define SCHUNK (SS / NSPLIT)   // 256

// Scratch (allocation-free rule: __device__ globals)
__device__ float g_att_h[BB * HH];            // 128 KB
__device__ float g_score[BB * SS];            // 512 KB (raw scores; softmax fused into k4)
__device__ float g_partial[NSPLIT * BB * RR]; // 2 MB

__device__ __forceinline__ float fast_tanh(float x) {
    float y;
    asm("tanh.approx.f32 %0, %1;" : "=f"(y) : "f"(x));
    return y;
}

// ---------------------------------------------------------------------------
// K1: att_h[b,j] = dot(h[b,:], W[j,:]) + bias[j]
// grid (HH/8 = 64 j-groups, 4 b-groups), block 256 (8 warps; warp w owns j).
// Each block caches its 8 W rows in smem ONCE (32 KB) and loops 16 batches
// with a double-buffered h row. W L2 traffic: 8 MB total (was 128 MB).
// ---------------------------------------------------------------------------
__global__ void k1_att_h(const float* __restrict__ h,
                         const float* __restrict__ W,
                         const float* __restrict__ bias) {
    const int warp = threadIdx.x >> 5;
    const int lane = threadIdx.x & 31;
    const int j    = blockIdx.x * 8 + warp;

    __shared__ float sW[8 * RR];      // 32 KB: this block's 8 W rows
    __shared__ float sh[2][RR];       // double-buffered h row (2 x 4 KB)

    // cooperative linear copy of 8 contiguous W rows
    const float4* Wg = (const float4*)(W + (size_t)blockIdx.x * 8 * RR);
#pragma unroll
    for (int k = 0; k < 8; k++)
        ((float4*)sW)[threadIdx.x + k * 256] = Wg[threadIdx.x + k * 256];

    const float bj = bias[j];

    for (int it = 0; it < 16; it++) {
        const int b   = blockIdx.y * 16 + it;
        const int buf = it & 1;
        ((float4*)sh[buf])[threadIdx.x] =
            ((const float4*)(h + (size_t)b * RR))[threadIdx.x];
        __syncthreads();

        float acc = 0.f;
        const float4* wr = (const float4*)(sW + warp * RR);
        const float4* hr = (const float4*)sh[buf];
#pragma unroll
        for (int i = 0; i < RR / 128; i++) {          // 8 iterations
            float4 w4 = wr[i * 32 + lane];
            float4 h4 = hr[i * 32 + lane];
            acc += w4.x * h4.x + w4.y * h4.y + w4.z * h4.z + w4.w * h4.w;
        }
#pragma unroll
        for (int o = 16; o; o >>= 1) acc += __shfl_down_sync(0xFFFFFFFFu, acc, o);
        if (lane == 0) g_att_h[b * HH + j] = acc + bj;
    }
}

// ---------------------------------------------------------------------------
// K2: score[b,s] = sum_h tanh(p[b,s,h] + att_h[b,h]) * w_alpha[h]
// (b_alpha dropped: a constant shift cancels in softmax)
// grid (B, S/8), block 256 (8 warps, one s per warp). 256 MB streaming read.
// tanh via MUFU.TANH so the kernel stays HBM-bound.
// ---------------------------------------------------------------------------
__global__ void k2_scores(const float* __restrict__ p,
                          const float* __restrict__ w_alpha) {
    const int b = blockIdx.x;

    __shared__ float s_ah[HH];
    __shared__ float s_wa[HH];
    for (int i = threadIdx.x; i < HH / 4; i += blockDim.x) {
        ((float4*)s_ah)[i] = ((const float4*)(g_att_h + (size_t)b * HH))[i];
        ((float4*)s_wa)[i] = ((const float4*)w_alpha)[i];
    }
    __syncthreads();

    const int warp = threadIdx.x >> 5;
    const int lane = threadIdx.x & 31;
    const int s    = blockIdx.y * 8 + warp;

    const float4* pr = (const float4*)(p + ((size_t)b * SS + s) * HH);

    float acc = 0.f;
#pragma unroll
    for (int i = 0; i < HH / 128; i++) {           // 4 iterations
        float4 p4 = pr[i * 32 + lane];
        int k = (i * 32 + lane) * 4;
        acc += fast_tanh(p4.x + s_ah[k])     * s_wa[k];
        acc += fast_tanh(p4.y + s_ah[k + 1]) * s_wa[k + 1];
        acc += fast_tanh(p4.z + s_ah[k + 2]) * s_wa[k + 2];
        acc += fast_tanh(p4.w + s_ah[k + 3]) * s_wa[k + 3];
    }
#pragma unroll
    for (int o = 16; o; o >>= 1) acc += __shfl_down_sync(0xFFFFFFFFu, acc, o);
    if (lane == 0) g_score[b * SS + s] = acc;
}

// ---------------------------------------------------------------------------
// K4: fused softmax + partial weighted sums over an S-chunk (S-split — the
// layout that hits 84% DRAM). grid (B, NSPLIT), block 256.
// Prologue: each block redundantly computes its batch row's masked softmax.
// softmax -> *mask -> renorm  ==  e_i*m_i / sum_j(e_j*m_j)  (max-subtracted).
// Main loop: dense 4 KB-row streaming of att_feats (512 MB).
// ---------------------------------------------------------------------------
__global__ void k4_wsum(const float* __restrict__ feats,
                        const int* __restrict__ mask) {
    const int b   = blockIdx.x;
    const int sp  = blockIdx.y;
    const int s0  = sp * SCHUNK;
    const int tid = threadIdx.x;

    __shared__ float sw[SCHUNK];
    __shared__ float red[8];

    // --- load all SS scores for this batch row: thread tid owns tid + k*256
    float v[NSPLIT];
    int   m[NSPLIT];
#pragma unroll
    for (int k = 0; k < NSPLIT; k++) {
        v[k] = g_score[b * SS + k * 256 + tid];
        m[k] = mask[b * SS + k * 256 + tid];
    }

    // --- block max (over all scores, matching reference stability)
    float mx = v[0];
#pragma unroll
    for (int k = 1; k < NSPLIT; k++) mx = fmaxf(mx, v[k]);
#pragma unroll
    for (int o = 16; o; o >>= 1) mx = fmaxf(mx, __shfl_xor_sync(0xFFFFFFFFu, mx, o));
    if ((tid & 31) == 0) red[tid >> 5] = mx;
    __syncthreads();
    mx = fmaxf(fmaxf(fmaxf(red[0], red[1]), fmaxf(red[2], red[3])),
               fmaxf(fmaxf(red[4], red[5]), fmaxf(red[6], red[7])));
    __syncthreads();

    // --- masked exponentials + block sum
    float e[NSPLIT];
    float sum = 0.f;
#pragma unroll
    for (int k = 0; k < NSPLIT; k++) {
        e[k] = m[k] ? __expf(v[k] - mx) : 0.f;
        sum += e[k];
    }
#pragma unroll
    for (int o = 16; o; o >>= 1) sum += __shfl_xor_sync(0xFFFFFFFFu, sum, o);
    if ((tid & 31) == 0) red[tid >> 5] = sum;
    __syncthreads();
    sum = red[0] + red[1] + red[2] + red[3] + red[4] + red[5] + red[6] + red[7];
    const float inv = 1.f / sum;

    // this block's chunk weights: chunk sp covers indices sp*256 + tid -> k == sp
    sw[tid] = e[sp] * inv;
    __syncthreads();

    // --- streaming weighted sum
    const float4* base = (const float4*)(feats + ((size_t)b * SS + s0) * RR) + tid;

    float4 acc = make_float4(0.f, 0.f, 0.f, 0.f);
#pragma unroll 4
    for (int i = 0; i < SCHUNK; i++) {
        float4 f = base[(size_t)i * (RR / 4)];
        float w = sw[i];
        acc.x += w * f.x; acc.y += w * f.y; acc.z += w * f.z; acc.w += w * f.w;
    }
    ((float4*)(g_partial + ((size_t)sp * BB + b) * RR))[tid] = acc;
}

// ---------------------------------------------------------------------------
// K5: reduce NSPLIT partials into the output.
// grid 256 x block 64 (wide SM spread; partials are L2-hot), float4/thread.
// ---------------------------------------------------------------------------
__global__ void k5_reduce(float* __restrict__ out) {
    const int idx = blockIdx.x * 64 + threadIdx.x;   // float4 index into [B*R/4]
    float4 acc = make_float4(0.f, 0.f, 0.f, 0.f);
#pragma unroll
    for (int sp = 0; sp < NSPLIT; sp++) {
        float4 f = ((const float4*)(g_partial + (size_t)sp * BB * RR))[idx];
        acc.x += f.x; acc.y += f.y; acc.z += f.z; acc.w += f.w;
    }
    ((float4*)out)[idx] = acc;
}

// ---------------------------------------------------------------------------
extern "C" void kernel_launch(void* const* d_in, const int* in_sizes, int n_in,
                              void* d_out, int out_size) {
    const float* h         = (const float*)d_in[0];
    const float* att_feats = (const float*)d_in[1];
    const float* p_att     = (const float*)d_in[2];
    const int*   masks     = (const int*)  d_in[3];
    const float* W         = (const float*)d_in[4];
    const float* b_h2att   = (const float*)d_in[5];
    const float* w_alpha   = (const float*)d_in[6];
    // d_in[7] = b_alpha: unused (constant shift cancels in softmax)
    float*       out       = (float*)d_out;

    k1_att_h  <<<dim3(HH / 8, 4),  256>>>(h, W, b_h2att);
    k2_scores <<<dim3(BB, SS / 8), 256>>>(p_att, w_alpha);
    k4_wsum   <<<dim3(BB, NSPLIT), 256>>>(att_feats, masks);
    k5_reduce <<<BB * RR / 256,     64>>>(out);
}

// round 9
// speedup vs baseline: 1.1308x; 1.0292x over previous
#include <cuda_runtime.h>
#include <cuda_bf16.h>

#define BB 64
#define SS 2048
#define RR 1024
#define HH 512
#define NOWN 8                  // scores owned per thread in softmax prologue
#define NSPLIT 16               // S-chunks in k4 (1024 blocks -> 6.9 waves)
#define SCHUNK (SS / NSPLIT)    // 128

// Scratch (allocation-free rule: __device__ globals)
__device__ float g_att_h[BB * HH];   // 128 KB
__device__ float g_score[BB * SS];   // 512 KB (raw scores; softmax fused into k4)

__device__ __forceinline__ float fast_tanh(float x) {
    float y;
    asm("tanh.approx.f32 %0, %1;" : "=f"(y) : "f"(x));
    return y;
}

// ---------------------------------------------------------------------------
// K1: att_h[b,j] = dot(h[b,:], W[j,:]) + bias[j]   (+ zero-init of d_out)
// grid (HH/8 = 64 j-groups, 4 b-groups), block 256 (8 warps; warp w owns j).
// Each block caches its 8 W rows in smem ONCE (32 KB) and loops 16 batches
// with a double-buffered h row. W L2 traffic: 8 MB total.
// Also zeroes d_out (256 blocks x 256 threads = exactly B*R floats) so k4
// can accumulate into it with red.global.add.
// ---------------------------------------------------------------------------
__global__ void k1_att_h(const float* __restrict__ h,
                         const float* __restrict__ W,
                         const float* __restrict__ bias,
                         float* __restrict__ out) {
    const int warp = threadIdx.x >> 5;
    const int lane = threadIdx.x & 31;
    const int j    = blockIdx.x * 8 + warp;

    // zero d_out: linear block id over (gridDim.x=64, gridDim.y=4)
    out[((size_t)blockIdx.y * 64 + blockIdx.x) * 256 + threadIdx.x] = 0.f;

    __shared__ float sW[8 * RR];      // 32 KB: this block's 8 W rows
    __shared__ float sh[2][RR];       // double-buffered h row (2 x 4 KB)

    const float4* Wg = (const float4*)(W + (size_t)blockIdx.x * 8 * RR);
#pragma unroll
    for (int k = 0; k < 8; k++)
        ((float4*)sW)[threadIdx.x + k * 256] = Wg[threadIdx.x + k * 256];

    const float bj = bias[j];

    for (int it = 0; it < 16; it++) {
        const int b   = blockIdx.y * 16 + it;
        const int buf = it & 1;
        ((float4*)sh[buf])[threadIdx.x] =
            ((const float4*)(h + (size_t)b * RR))[threadIdx.x];
        __syncthreads();

        float acc = 0.f;
        const float4* wr = (const float4*)(sW + warp * RR);
        const float4* hr = (const float4*)sh[buf];
#pragma unroll
        for (int i = 0; i < RR / 128; i++) {          // 8 iterations
            float4 w4 = wr[i * 32 + lane];
            float4 h4 = hr[i * 32 + lane];
            acc += w4.x * h4.x + w4.y * h4.y + w4.z * h4.z + w4.w * h4.w;
        }
#pragma unroll
        for (int o = 16; o; o >>= 1) acc += __shfl_down_sync(0xFFFFFFFFu, acc, o);
        if (lane == 0) g_att_h[b * HH + j] = acc + bj;
    }
}

// ---------------------------------------------------------------------------
// K2: score[b,s] = sum_h tanh(p[b,s,h] + att_h[b,h]) * w_alpha[h]
// (b_alpha dropped: a constant shift cancels in softmax)
// grid (B, S/8), block 256 (8 warps, one s per warp). 256 MB streaming read.
// tanh via MUFU.TANH so the kernel stays HBM-bound.
// ---------------------------------------------------------------------------
__global__ void k2_scores(const float* __restrict__ p,
                          const float* __restrict__ w_alpha) {
    const int b = blockIdx.x;

    __shared__ float s_ah[HH];
    __shared__ float s_wa[HH];
    for (int i = threadIdx.x; i < HH / 4; i += blockDim.x) {
        ((float4*)s_ah)[i] = ((const float4*)(g_att_h + (size_t)b * HH))[i];
        ((float4*)s_wa)[i] = ((const float4*)w_alpha)[i];
    }
    __syncthreads();

    const int warp = threadIdx.x >> 5;
    const int lane = threadIdx.x & 31;
    const int s    = blockIdx.y * 8 + warp;

    const float4* pr = (const float4*)(p + ((size_t)b * SS + s) * HH);

    float acc = 0.f;
#pragma unroll
    for (int i = 0; i < HH / 128; i++) {           // 4 iterations
        float4 p4 = pr[i * 32 + lane];
        int k = (i * 32 + lane) * 4;
        acc += fast_tanh(p4.x + s_ah[k])     * s_wa[k];
        acc += fast_tanh(p4.y + s_ah[k + 1]) * s_wa[k + 1];
        acc += fast_tanh(p4.z + s_ah[k + 2]) * s_wa[k + 2];
        acc += fast_tanh(p4.w + s_ah[k + 3]) * s_wa[k + 3];
    }
#pragma unroll
    for (int o = 16; o; o >>= 1) acc += __shfl_down_sync(0xFFFFFFFFu, acc, o);
    if (lane == 0) g_score[b * SS + s] = acc;
}

// ---------------------------------------------------------------------------
// K4: fused softmax + partial weighted sums over an S-chunk (S-split), with
// direct red.global accumulation into d_out — no reduce kernel.
// grid (B, NSPLIT=16), block 256.
// Prologue: each block redundantly computes its batch row's masked softmax
// into smem (full 8 KB weight row).
// softmax -> *mask -> renorm  ==  e_i*m_i / sum_j(e_j*m_j)  (max-subtracted).
// Main loop: dense 4 KB-row streaming of att_feats (512 MB total).
// ---------------------------------------------------------------------------
__global__ void k4_wsum(const float* __restrict__ feats,
                        const int* __restrict__ mask,
                        float* __restrict__ out) {
    const int b   = blockIdx.x;
    const int sp  = blockIdx.y;
    const int s0  = sp * SCHUNK;
    const int tid = threadIdx.x;

    __shared__ float sw[SS];       // 8 KB: full weight row
    __shared__ float red[8];

    // --- load all SS scores for this batch row: thread tid owns tid + k*256
    float v[NOWN];
    int   m[NOWN];
#pragma unroll
    for (int k = 0; k < NOWN; k++) {
        v[k] = g_score[b * SS + k * 256 + tid];
        m[k] = mask[b * SS + k * 256 + tid];
    }

    // --- block max (over all scores, matching reference stability)
    float mx = v[0];
#pragma unroll
    for (int k = 1; k < NOWN; k++) mx = fmaxf(mx, v[k]);
#pragma unroll
    for (int o = 16; o; o >>= 1) mx = fmaxf(mx, __shfl_xor_sync(0xFFFFFFFFu, mx, o));
    if ((tid & 31) == 0) red[tid >> 5] = mx;
    __syncthreads();
    mx = fmaxf(fmaxf(fmaxf(red[0], red[1]), fmaxf(red[2], red[3])),
               fmaxf(fmaxf(red[4], red[5]), fmaxf(red[6], red[7])));
    __syncthreads();

    // --- masked exponentials + block sum
    float e[NOWN];
    float sum = 0.f;
#pragma unroll
    for (int k = 0; k < NOWN; k++) {
        e[k] = m[k] ? __expf(v[k] - mx) : 0.f;
        sum += e[k];
    }
#pragma unroll
    for (int o = 16; o; o >>= 1) sum += __shfl_xor_sync(0xFFFFFFFFu, sum, o);
    if ((tid & 31) == 0) red[tid >> 5] = sum;
    __syncthreads();
    sum = red[0] + red[1] + red[2] + red[3] + red[4] + red[5] + red[6] + red[7];
    const float inv = 1.f / sum;

#pragma unroll
    for (int k = 0; k < NOWN; k++) sw[k * 256 + tid] = e[k] * inv;
    __syncthreads();

    // --- streaming weighted sum over this block's 128-row chunk
    const float4* base = (const float4*)(feats + ((size_t)b * SS + s0) * RR) + tid;
    const float*  wrow = sw + s0;

    float4 acc = make_float4(0.f, 0.f, 0.f, 0.f);
#pragma unroll 4
    for (int i = 0; i < SCHUNK; i++) {
        float4 f = base[(size_t)i * (RR / 4)];
        float w = wrow[i];
        acc.x += w * f.x; acc.y += w * f.y; acc.z += w * f.z; acc.w += w * f.w;
    }

    // --- accumulate directly into the output (REDG; 16 contributors/address)
    float* o = out + (size_t)b * RR + tid * 4;
    atomicAdd(o + 0, acc.x);
    atomicAdd(o + 1, acc.y);
    atomicAdd(o + 2, acc.z);
    atomicAdd(o + 3, acc.w);
}

// ---------------------------------------------------------------------------
extern "C" void kernel_launch(void* const* d_in, const int* in_sizes, int n_in,
                              void* d_out, int out_size) {
    const float* h         = (const float*)d_in[0];
    const float* att_feats = (const float*)d_in[1];
    const float* p_att     = (const float*)d_in[2];
    const int*   masks     = (const int*)  d_in[3];
    const float* W         = (const float*)d_in[4];
    const float* b_h2att   = (const float*)d_in[5];
    const float* w_alpha   = (const float*)d_in[6];
    // d_in[7] = b_alpha: unused (constant shift cancels in softmax)
    float*       out       = (float*)d_out;

    k1_att_h  <<<dim3(HH / 8, 4),  256>>>(h, W, b_h2att, out);
    k2_scores <<<dim3(BB, SS / 8), 256>>>(p_att, w_alpha);
    k4_wsum   <<<dim3(BB, NSPLIT), 256>>>(att_feats, masks, out);
}

// round 10
// speedup vs baseline: 1.1819x; 1.0452x over previous
#include <cuda_runtime.h>
#include <cuda_bf16.h>

#define BB 64
#define SS 2048
#define RR 1024
#define HH 512
#define NOWN 8                  // scores owned per thread in softmax prologue
#define NSPLIT 16               // S-chunks in k4 (1024 blocks -> 6.9 waves)
#define SCHUNK (SS / NSPLIT)    // 128

// Scratch (allocation-free rule: __device__ globals)
__device__ float g_att_h[BB * HH];   // 128 KB
__device__ float g_score[BB * SS];   // 512 KB (raw scores; softmax fused into k4)

__device__ __forceinline__ float fast_tanh(float x) {
    float y;
    asm("tanh.approx.f32 %0, %1;" : "=f"(y) : "f"(x));
    return y;
}

// ---------------------------------------------------------------------------
// K1: att_h[b,j] = dot(h[b,:], W[j,:]) + bias[j]   (+ zero-init of d_out)
// grid (HH/8 = 64 j-groups, BB/4 = 16 b-groups) = 1024 blocks, block 256.
// Each block: 8 W rows (32 KB) + 4 h rows (16 KB) loaded up front, ONE
// __syncthreads, then warp w computes j = bx*8+w against 4 batches with 4
// independent accumulators (no further barriers). W L2 traffic: 32 MB total.
// First 256 blocks also zero d_out for k4's red.global accumulation.
// ---------------------------------------------------------------------------
__global__ void k1_att_h(const float* __restrict__ h,
                         const float* __restrict__ W,
                         const float* __restrict__ bias,
                         float* __restrict__ out) {
    const int warp = threadIdx.x >> 5;
    const int lane = threadIdx.x & 31;
    const int j    = blockIdx.x * 8 + warp;
    const int b0   = blockIdx.y * 4;

    // zero d_out: first 256 blocks (by = 0..3) cover exactly B*R floats
    if (blockIdx.y < 4)
        out[((size_t)blockIdx.y * 64 + blockIdx.x) * 256 + threadIdx.x] = 0.f;

    __shared__ float sW[8 * RR];      // 32 KB: this block's 8 W rows
    __shared__ float sh[4 * RR];      // 16 KB: this block's 4 h rows

    const float4* Wg = (const float4*)(W + (size_t)blockIdx.x * 8 * RR);
#pragma unroll
    for (int k = 0; k < 8; k++)
        ((float4*)sW)[threadIdx.x + k * 256] = Wg[threadIdx.x + k * 256];

    const float4* Hg = (const float4*)(h + (size_t)b0 * RR);
#pragma unroll
    for (int k = 0; k < 4; k++)
        ((float4*)sh)[threadIdx.x + k * 256] = Hg[threadIdx.x + k * 256];

    __syncthreads();

    const float4* wr = (const float4*)(sW + warp * RR);
    const float4* h0 = (const float4*)(sh);
    const float4* h1 = (const float4*)(sh + RR);
    const float4* h2 = (const float4*)(sh + 2 * RR);
    const float4* h3 = (const float4*)(sh + 3 * RR);

    float a0 = 0.f, a1 = 0.f, a2 = 0.f, a3 = 0.f;
#pragma unroll
    for (int i = 0; i < RR / 128; i++) {          // 8 iterations
        const int idx = i * 32 + lane;
        float4 w4 = wr[idx];
        float4 x;
        x = h0[idx]; a0 += w4.x * x.x + w4.y * x.y + w4.z * x.z + w4.w * x.w;
        x = h1[idx]; a1 += w4.x * x.x + w4.y * x.y + w4.z * x.z + w4.w * x.w;
        x = h2[idx]; a2 += w4.x * x.x + w4.y * x.y + w4.z * x.z + w4.w * x.w;
        x = h3[idx]; a3 += w4.x * x.x + w4.y * x.y + w4.z * x.z + w4.w * x.w;
    }
#pragma unroll
    for (int o = 16; o; o >>= 1) {
        a0 += __shfl_down_sync(0xFFFFFFFFu, a0, o);
        a1 += __shfl_down_sync(0xFFFFFFFFu, a1, o);
        a2 += __shfl_down_sync(0xFFFFFFFFu, a2, o);
        a3 += __shfl_down_sync(0xFFFFFFFFu, a3, o);
    }
    if (lane == 0) {
        const float bj = bias[j];
        g_att_h[(b0 + 0) * HH + j] = a0 + bj;
        g_att_h[(b0 + 1) * HH + j] = a1 + bj;
        g_att_h[(b0 + 2) * HH + j] = a2 + bj;
        g_att_h[(b0 + 3) * HH + j] = a3 + bj;
    }
}

// ---------------------------------------------------------------------------
// K2: score[b,s] = sum_h tanh(p[b,s,h] + att_h[b,h]) * w_alpha[h]
// (b_alpha dropped: a constant shift cancels in softmax)
// grid (B, S/8), block 256 (8 warps, one s per warp). 256 MB streaming read.
// tanh via MUFU.TANH so the kernel stays HBM-bound.
// ---------------------------------------------------------------------------
__global__ void k2_scores(const float* __restrict__ p,
                          const float* __restrict__ w_alpha) {
    const int b = blockIdx.x;

    __shared__ float s_ah[HH];
    __shared__ float s_wa[HH];
    for (int i = threadIdx.x; i < HH / 4; i += blockDim.x) {
        ((float4*)s_ah)[i] = ((const float4*)(g_att_h + (size_t)b * HH))[i];
        ((float4*)s_wa)[i] = ((const float4*)w_alpha)[i];
    }
    __syncthreads();

    const int warp = threadIdx.x >> 5;
    const int lane = threadIdx.x & 31;
    const int s    = blockIdx.y * 8 + warp;

    const float4* pr = (const float4*)(p + ((size_t)b * SS + s) * HH);

    float acc = 0.f;
#pragma unroll
    for (int i = 0; i < HH / 128; i++) {           // 4 iterations
        float4 p4 = pr[i * 32 + lane];
        int k = (i * 32 + lane) * 4;
        acc += fast_tanh(p4.x + s_ah[k])     * s_wa[k];
        acc += fast_tanh(p4.y + s_ah[k + 1]) * s_wa[k + 1];
        acc += fast_tanh(p4.z + s_ah[k + 2]) * s_wa[k + 2];
        acc += fast_tanh(p4.w + s_ah[k + 3]) * s_wa[k + 3];
    }
#pragma unroll
    for (int o = 16; o; o >>= 1) acc += __shfl_down_sync(0xFFFFFFFFu, acc, o);
    if (lane == 0) g_score[b * SS + s] = acc;
}

// ---------------------------------------------------------------------------
// K4: fused softmax + partial weighted sums over an S-chunk (S-split), with
// direct red.global accumulation into d_out — no reduce kernel.
// grid (B, NSPLIT=16), block 256.
// Prologue: each block redundantly computes its batch row's masked softmax
// into smem (full 8 KB weight row).
// softmax -> *mask -> renorm  ==  e_i*m_i / sum_j(e_j*m_j)  (max-subtracted).
// Main loop: dense 4 KB-row streaming of att_feats (512 MB total).
// ---------------------------------------------------------------------------
__global__ void k4_wsum(const float* __restrict__ feats,
                        const int* __restrict__ mask,
                        float* __restrict__ out) {
    const int b   = blockIdx.x;
    const int sp  = blockIdx.y;
    const int s0  = sp * SCHUNK;
    const int tid = threadIdx.x;

    __shared__ float sw[SS];       // 8 KB: full weight row
    __shared__ float red[8];

    // --- load all SS scores for this batch row: thread tid owns tid + k*256
    float v[NOWN];
    int   m[NOWN];
#pragma unroll
    for (int k = 0; k < NOWN; k++) {
        v[k] = g_score[b * SS + k * 256 + tid];
        m[k] = mask[b * SS + k * 256 + tid];
    }

    // --- block max (over all scores, matching reference stability)
    float mx = v[0];
#pragma unroll
    for (int k = 1; k < NOWN; k++) mx = fmaxf(mx, v[k]);
#pragma unroll
    for (int o = 16; o; o >>= 1) mx = fmaxf(mx, __shfl_xor_sync(0xFFFFFFFFu, mx, o));
    if ((tid & 31) == 0) red[tid >> 5] = mx;
    __syncthreads();
    mx = fmaxf(fmaxf(fmaxf(red[0], red[1]), fmaxf(red[2], red[3])),
               fmaxf(fmaxf(red[4], red[5]), fmaxf(red[6], red[7])));
    __syncthreads();

    // --- masked exponentials + block sum
    float e[NOWN];
    float sum = 0.f;
#pragma unroll
    for (int k = 0; k < NOWN; k++) {
        e[k] = m[k] ? __expf(v[k] - mx) : 0.f;
        sum += e[k];
    }
#pragma unroll
    for (int o = 16; o; o >>= 1) sum += __shfl_xor_sync(0xFFFFFFFFu, sum, o);
    if ((tid & 31) == 0) red[tid >> 5] = sum;
    __syncthreads();
    sum = red[0] + red[1] + red[2] + red[3] + red[4] + red[5] + red[6] + red[7];
    const float inv = 1.f / sum;

#pragma unroll
    for (int k = 0; k < NOWN; k++) sw[k * 256 + tid] = e[k] * inv;
    __syncthreads();

    // --- streaming weighted sum over this block's 128-row chunk
    const float4* base = (const float4*)(feats + ((size_t)b * SS + s0) * RR) + tid;
    const float*  wrow = sw + s0;

    float4 acc = make_float4(0.f, 0.f, 0.f, 0.f);
#pragma unroll 4
    for (int i = 0; i < SCHUNK; i++) {
        float4 f = base[(size_t)i * (RR / 4)];
        float w = wrow[i];
        acc.x += w * f.x; acc.y += w * f.y; acc.z += w * f.z; acc.w += w * f.w;
    }

    // --- accumulate directly into the output (REDG; 16 contributors/address)
    float* o = out + (size_t)b * RR + tid * 4;
    atomicAdd(o + 0, acc.x);
    atomicAdd(o + 1, acc.y);
    atomicAdd(o + 2, acc.z);
    atomicAdd(o + 3, acc.w);
}

// ---------------------------------------------------------------------------
extern "C" void kernel_launch(void* const* d_in, const int* in_sizes, int n_in,
                              void* d_out, int out_size) {
    const float* h         = (const float*)d_in[0];
    const float* att_feats = (const float*)d_in[1];
    const float* p_att     = (const float*)d_in[2];
    const int*   masks     = (const int*)  d_in[3];
    const float* W         = (const float*)d_in[4];
    const float* b_h2att   = (const float*)d_in[5];
    const float* w_alpha   = (const float*)d_in[6];
    // d_in[7] = b_alpha: unused (constant shift cancels in softmax)
    float*       out       = (float*)d_out;

    k1_att_h  <<<dim3(HH / 8, BB / 4), 256>>>(h, W, b_h2att, out);
    k2_scores <<<dim3(BB, SS / 8),     256>>>(p_att, w_alpha);
    k4_wsum   <<<dim3(BB, NSPLIT),     256>>>(att_feats, masks, out);
}

// round 11
// speedup vs baseline: 1.1961x; 1.0120x over previous
#include <cuda_runtime.h>
#include <cuda_bf16.h>

#define BB 64
#define SS 2048
#define RR 1024
#define HH 512
#define NOWN 8                  // scores owned per thread in softmax prologue
#define NSPLIT 16               // S-chunks in k4 (1024 blocks -> 6.9 waves)
#define SCHUNK (SS / NSPLIT)    // 128

// Scratch (allocation-free rule: __device__ globals)
__device__ float g_att_h[BB * HH];   // 128 KB
__device__ float g_score[BB * SS];   // 512 KB (raw scores; softmax fused into k4)

__device__ __forceinline__ float fast_tanh(float x) {
    float y;
    asm("tanh.approx.f32 %0, %1;" : "=f"(y) : "f"(x));
    return y;
}

// ---------------------------------------------------------------------------
// K1: att_h[b,j] = dot(h[b,:], W[j,:]) + bias[j]   (+ zero-init of d_out)
// grid (HH/8 = 64 j-groups, BB/4 = 16 b-groups) = 1024 blocks, block 256.
// Warp w owns j = bx*8+w and reads its W row DIRECTLY from gmem (coalesced
// LDG.128, L2-resident 2 MB — no smem staging round-trip). Only the 4 h rows
// are staged in smem (16 KB -> high occupancy). Each W float4 is reused
// across 4 batch accumulators in registers (ILP 4).
// First 256 blocks also zero d_out for k4's red.global accumulation.
// ---------------------------------------------------------------------------
__global__ void k1_att_h(const float* __restrict__ h,
                         const float* __restrict__ W,
                         const float* __restrict__ bias,
                         float* __restrict__ out) {
    const int warp = threadIdx.x >> 5;
    const int lane = threadIdx.x & 31;
    const int j    = blockIdx.x * 8 + warp;
    const int b0   = blockIdx.y * 4;

    // zero d_out: first 256 blocks (by = 0..3) cover exactly B*R floats
    if (blockIdx.y < 4)
        out[((size_t)blockIdx.y * 64 + blockIdx.x) * 256 + threadIdx.x] = 0.f;

    __shared__ float sh[4 * RR];      // 16 KB: this block's 4 h rows

    const float4* Hg = (const float4*)(h + (size_t)b0 * RR);
#pragma unroll
    for (int k = 0; k < 4; k++)
        ((float4*)sh)[threadIdx.x + k * 256] = Hg[threadIdx.x + k * 256];

    __syncthreads();

    const float4* wr = (const float4*)(W + (size_t)j * RR);
    const float4* h0 = (const float4*)(sh);
    const float4* h1 = (const float4*)(sh + RR);
    const float4* h2 = (const float4*)(sh + 2 * RR);
    const float4* h3 = (const float4*)(sh + 3 * RR);

    float a0 = 0.f, a1 = 0.f, a2 = 0.f, a3 = 0.f;
#pragma unroll
    for (int i = 0; i < RR / 128; i++) {          // 8 iterations
        const int idx = i * 32 + lane;
        float4 w4 = wr[idx];                       // LDG.128, L2-hot
        float4 x;
        x = h0[idx]; a0 += w4.x * x.x + w4.y * x.y + w4.z * x.z + w4.w * x.w;
        x = h1[idx]; a1 += w4.x * x.x + w4.y * x.y + w4.z * x.z + w4.w * x.w;
        x = h2[idx]; a2 += w4.x * x.x + w4.y * x.y + w4.z * x.z + w4.w * x.w;
        x = h3[idx]; a3 += w4.x * x.x + w4.y * x.y + w4.z * x.z + w4.w * x.w;
    }
#pragma unroll
    for (int o = 16; o; o >>= 1) {
        a0 += __shfl_down_sync(0xFFFFFFFFu, a0, o);
        a1 += __shfl_down_sync(0xFFFFFFFFu, a1, o);
        a2 += __shfl_down_sync(0xFFFFFFFFu, a2, o);
        a3 += __shfl_down_sync(0xFFFFFFFFu, a3, o);
    }
    if (lane == 0) {
        const float bj = bias[j];
        g_att_h[(b0 + 0) * HH + j] = a0 + bj;
        g_att_h[(b0 + 1) * HH + j] = a1 + bj;
        g_att_h[(b0 + 2) * HH + j] = a2 + bj;
        g_att_h[(b0 + 3) * HH + j] = a3 + bj;
    }
}

// ---------------------------------------------------------------------------
// K2: score[b,s] = sum_h tanh(p[b,s,h] + att_h[b,h]) * w_alpha[h]
// (b_alpha dropped: a constant shift cancels in softmax)
// grid (B, S/8), block 256 (8 warps, one s per warp). 256 MB streaming read.
// tanh via MUFU.TANH so the kernel stays HBM-bound.
// ---------------------------------------------------------------------------
__global__ void k2_scores(const float* __restrict__ p,
                          const float* __restrict__ w_alpha) {
    const int b = blockIdx.x;

    __shared__ float s_ah[HH];
    __shared__ float s_wa[HH];
    for (int i = threadIdx.x; i < HH / 4; i += blockDim.x) {
        ((float4*)s_ah)[i] = ((const float4*)(g_att_h + (size_t)b * HH))[i];
        ((float4*)s_wa)[i] = ((const float4*)w_alpha)[i];
    }
    __syncthreads();

    const int warp = threadIdx.x >> 5;
    const int lane = threadIdx.x & 31;
    const int s    = blockIdx.y * 8 + warp;

    const float4* pr = (const float4*)(p + ((size_t)b * SS + s) * HH);

    float acc = 0.f;
#pragma unroll
    for (int i = 0; i < HH / 128; i++) {           // 4 iterations
        float4 p4 = pr[i * 32 + lane];
        int k = (i * 32 + lane) * 4;
        acc += fast_tanh(p4.x + s_ah[k])     * s_wa[k];
        acc += fast_tanh(p4.y + s_ah[k + 1]) * s_wa[k + 1];
        acc += fast_tanh(p4.z + s_ah[k + 2]) * s_wa[k + 2];
        acc += fast_tanh(p4.w + s_ah[k + 3]) * s_wa[k + 3];
    }
#pragma unroll
    for (int o = 16; o; o >>= 1) acc += __shfl_down_sync(0xFFFFFFFFu, acc, o);
    if (lane == 0) g_score[b * SS + s] = acc;
}

// ---------------------------------------------------------------------------
// K4: fused softmax + partial weighted sums over an S-chunk (S-split), with
// direct red.global accumulation into d_out — no reduce kernel.
// grid (B, NSPLIT=16), block 256.
// Prologue: each block redundantly computes its batch row's masked softmax
// into smem (full 8 KB weight row).
// softmax -> *mask -> renorm  ==  e_i*m_i / sum_j(e_j*m_j)  (max-subtracted).
// Main loop: dense 4 KB-row streaming of att_feats (512 MB total).
// ---------------------------------------------------------------------------
__global__ void k4_wsum(const float* __restrict__ feats,
                        const int* __restrict__ mask,
                        float* __restrict__ out) {
    const int b   = blockIdx.x;
    const int sp  = blockIdx.y;
    const int s0  = sp * SCHUNK;
    const int tid = threadIdx.x;

    __shared__ float sw[SS];       // 8 KB: full weight row
    __shared__ float red[8];

    // --- load all SS scores for this batch row: thread tid owns tid + k*256
    float v[NOWN];
    int   m[NOWN];
#pragma unroll
    for (int k = 0; k < NOWN; k++) {
        v[k] = g_score[b * SS + k * 256 + tid];
        m[k] = mask[b * SS + k * 256 + tid];
    }

    // --- block max (over all scores, matching reference stability)
    float mx = v[0];
#pragma unroll
    for (int k = 1; k < NOWN; k++) mx = fmaxf(mx, v[k]);
#pragma unroll
    for (int o = 16; o; o >>= 1) mx = fmaxf(mx, __shfl_xor_sync(0xFFFFFFFFu, mx, o));
    if ((tid & 31) == 0) red[tid >> 5] = mx;
    __syncthreads();
    mx = fmaxf(fmaxf(fmaxf(red[0], red[1]), fmaxf(red[2], red[3])),
               fmaxf(fmaxf(red[4], red[5]), fmaxf(red[6], red[7])));
    __syncthreads();

    // --- masked exponentials + block sum
    float e[NOWN];
    float sum = 0.f;
#pragma unroll
    for (int k = 0; k < NOWN; k++) {
        e[k] = m[k] ? __expf(v[k] - mx) : 0.f;
        sum += e[k];
    }
#pragma unroll
    for (int o = 16; o; o >>= 1) sum += __shfl_xor_sync(0xFFFFFFFFu, sum, o);
    if ((tid & 31) == 0) red[tid >> 5] = sum;
    __syncthreads();
    sum = red[0] + red[1] + red[2] + red[3] + red[4] + red[5] + red[6] + red[7];
    const float inv = 1.f / sum;

#pragma unroll
    for (int k = 0; k < NOWN; k++) sw[k * 256 + tid] = e[k] * inv;
    __syncthreads();

    // --- streaming weighted sum over this block's 128-row chunk
    const float4* base = (const float4*)(feats + ((size_t)b * SS + s0) * RR) + tid;
    const float*  wrow = sw + s0;

    float4 acc = make_float4(0.f, 0.f, 0.f, 0.f);
#pragma unroll 4
    for (int i = 0; i < SCHUNK; i++) {
        float4 f = base[(size_t)i * (RR / 4)];
        float w = wrow[i];
        acc.x += w * f.x; acc.y += w * f.y; acc.z += w * f.z; acc.w += w * f.w;
    }

    // --- accumulate directly into the output (REDG; 16 contributors/address)
    float* o = out + (size_t)b * RR + tid * 4;
    atomicAdd(o + 0, acc.x);
    atomicAdd(o + 1, acc.y);
    atomicAdd(o + 2, acc.z);
    atomicAdd(o + 3, acc.w);
}

// ---------------------------------------------------------------------------
extern "C" void kernel_launch(void* const* d_in, const int* in_sizes, int n_in,
                              void* d_out, int out_size) {
    const float* h         = (const float*)d_in[0];
    const float* att_feats = (const float*)d_in[1];
    const float* p_att     = (const float*)d_in[2];
    const int*   masks     = (const int*)  d_in[3];
    const float* W         = (const float*)d_in[4];
    const float* b_h2att   = (const float*)d_in[5];
    const float* w_alpha   = (const float*)d_in[6];
    // d_in[7] = b_alpha: unused (constant shift cancels in softmax)
    float*       out       = (float*)d_out;

    k1_att_h  <<<dim3(HH / 8, BB / 4), 256>>>(h, W, b_h2att, out);
    k2_scores <<<dim3(BB, SS / 8),     256>>>(p_att, w_alpha);
    k4_wsum   <<<dim3(BB, NSPLIT),     256>>>(att_feats, masks, out);
}